// round 1
// baseline (speedup 1.0000x reference)
#include <cuda_runtime.h>
#include <math.h>

#define MAXN 100000
#define MAXE 1600000
#define MAXET (MAXN + MAXE)

#define NEG_ATT 0.2f
#define NEG_ACT 0.01f

// ---------------- scratch (static __device__, no allocations) ----------------
__device__ float g_h1[MAXN * 128];   // layer-1 features h = x@W1
__device__ float g_hb[MAXN * 128];   // layer-1 output after attention+lrelu
__device__ float g_as1[MAXN * 8];
__device__ float g_ad1[MAXN * 8];
__device__ float g_h2[MAXN * 16];    // layer-2 features
__device__ float g_as2[MAXN];
__device__ float g_ad2[MAXN];
__device__ int   g_deg[MAXN];
__device__ int   g_rs[MAXN + 1];     // CSR row starts (by dst)
__device__ int   g_cur[MAXN];
__device__ int   g_esrc[MAXET];      // src node per incoming edge (self loop first)
__device__ int   g_bsum[256];

// ---------------- CSR build ----------------
__global__ void k_init_deg(int N) {
    int i = blockIdx.x * blockDim.x + threadIdx.x;
    if (i < N) g_deg[i] = 1;  // self loop
}

__global__ void k_hist(const int* __restrict__ dst, int E) {
    int e = blockIdx.x * blockDim.x + threadIdx.x;
    if (e < E) atomicAdd(&g_deg[dst[e]], 1);
}

__global__ void k_scan1(int N) {
    __shared__ int s[512];
    int t = threadIdx.x;
    int i = blockIdx.x * 512 + t;
    s[t] = (i < N) ? g_deg[i] : 0;
    __syncthreads();
    for (int off = 256; off; off >>= 1) {
        if (t < off) s[t] += s[t + off];
        __syncthreads();
    }
    if (t == 0) g_bsum[blockIdx.x] = s[0];
}

__global__ void k_scan2(int nb, int N) {
    int acc = 0;
    for (int b = 0; b < nb; b++) { int v = g_bsum[b]; g_bsum[b] = acc; acc += v; }
    g_rs[N] = acc;
}

__global__ void k_scan3(int N) {
    __shared__ int s[512];
    int t = threadIdx.x;
    int i = blockIdx.x * 512 + t;
    int v = (i < N) ? g_deg[i] : 0;
    s[t] = v;
    __syncthreads();
    for (int off = 1; off < 512; off <<= 1) {
        int x = (t >= off) ? s[t - off] : 0;
        __syncthreads();
        s[t] += x;
        __syncthreads();
    }
    int excl = s[t] - v;
    if (i < N) {
        int r = g_bsum[blockIdx.x] + excl;
        g_rs[i] = r;
        g_cur[i] = r + 1;   // slot 0 is the self loop
        g_esrc[r] = i;
    }
}

__global__ void k_scatter(const int* __restrict__ src, const int* __restrict__ dst, int E) {
    int e = blockIdx.x * blockDim.x + threadIdx.x;
    if (e < E) {
        int p = atomicAdd(&g_cur[dst[e]], 1);
        g_esrc[p] = src[e];
    }
}

// ---------------- GEMM1: h1 = x @ W1  ([N,128]@[128,128]) ----------------
// block = 128 threads (thread t = output column), 32 nodes per block.
__global__ void k_gemm1(const float* __restrict__ x, const float* __restrict__ W, int N) {
    __shared__ float xs[32 * 128];
    int t = threadIdx.x;
    int n0 = blockIdx.x * 32;
    const float4* x4 = (const float4*)x;
    float4* xs4 = (float4*)xs;
    for (int i = t; i < 32 * 32; i += 128) {
        int row = i >> 5, c4 = i & 31;
        float4 v = make_float4(0.f, 0.f, 0.f, 0.f);
        if (n0 + row < N) v = x4[(size_t)(n0 + row) * 32 + c4];
        xs4[i] = v;
    }
    __syncthreads();
    float acc[32];
#pragma unroll
    for (int i = 0; i < 32; i++) acc[i] = 0.f;
    for (int k = 0; k < 128; k += 4) {
        float w0 = W[(k + 0) * 128 + t];
        float w1 = W[(k + 1) * 128 + t];
        float w2 = W[(k + 2) * 128 + t];
        float w3 = W[(k + 3) * 128 + t];
        int k4 = k >> 2;
#pragma unroll
        for (int nl = 0; nl < 32; nl++) {
            float4 xv = xs4[nl * 32 + k4];
            acc[nl] = fmaf(xv.x, w0, acc[nl]);
            acc[nl] = fmaf(xv.y, w1, acc[nl]);
            acc[nl] = fmaf(xv.z, w2, acc[nl]);
            acc[nl] = fmaf(xv.w, w3, acc[nl]);
        }
    }
#pragma unroll
    for (int nl = 0; nl < 32; nl++) {
        int n = n0 + nl;
        if (n < N) g_h1[(size_t)n * 128 + t] = acc[nl];
    }
}

// ---------------- attention logits layer 1: as1/ad1[n,h] ----------------
__global__ void k_alpha1(const float* __restrict__ a1s, const float* __restrict__ a1d, int N) {
    int tid = blockIdx.x * blockDim.x + threadIdx.x;
    if (tid >= N * 8) return;
    int n = tid >> 3, h = tid & 7;
    const float4* hp = (const float4*)(g_h1 + (size_t)n * 128 + h * 16);
    const float4* asv = (const float4*)(a1s + h * 16);
    const float4* adv = (const float4*)(a1d + h * 16);
    float ss = 0.f, sd = 0.f;
#pragma unroll
    for (int j = 0; j < 4; j++) {
        float4 hv = hp[j];
        float4 a = __ldg(&asv[j]);
        float4 d = __ldg(&adv[j]);
        ss += hv.x * a.x + hv.y * a.y + hv.z * a.z + hv.w * a.w;
        sd += hv.x * d.x + hv.y * d.y + hv.z * d.z + hv.w * d.w;
    }
    g_as1[tid] = ss;
    g_ad1[tid] = sd;
}

// ---------------- layer-1 gather/softmax/aggregate: warp per node ----------------
__global__ void k_gather1(const float* __restrict__ b1, int N) {
    int warp = blockIdx.x * 8 + (threadIdx.x >> 5);
    if (warp >= N) return;
    int n = warp;
    int l = threadIdx.x & 31;
    int h = l >> 2;  // head for this lane (4 lanes = 16 floats per head)
    int beg = g_rs[n];
    int end = g_rs[n + 1];
    float adh = g_ad1[n * 8 + h];

    // pass 1: per-head max
    float mx = -1e30f;
    for (int i = beg; i < end; i++) {
        int s = g_esrc[i];
        float e = g_as1[s * 8 + h] + adh;
        e = (e > 0.f) ? e : NEG_ATT * e;
        mx = fmaxf(mx, e);
    }

    // pass 2: exp-weighted accumulate
    const float4* h14 = (const float4*)g_h1;
    float4 acc = make_float4(0.f, 0.f, 0.f, 0.f);
    float ds = 0.f;
    int s_next = g_esrc[beg];
    for (int i = beg; i < end; i++) {
        int s = s_next;
        if (i + 1 < end) s_next = g_esrc[i + 1];
        float e = g_as1[s * 8 + h] + adh;
        e = (e > 0.f) ? e : NEG_ATT * e;
        float ex = __expf(e - mx);
        float4 hv = h14[(size_t)s * 32 + l];
        acc.x = fmaf(hv.x, ex, acc.x);
        acc.y = fmaf(hv.y, ex, acc.y);
        acc.z = fmaf(hv.z, ex, acc.z);
        acc.w = fmaf(hv.w, ex, acc.w);
        ds += ex;
    }
    float inv = 1.f / ds;
    float4 bb = ((const float4*)b1)[l];
    float4 o;
    o.x = acc.x * inv + bb.x;
    o.y = acc.y * inv + bb.y;
    o.z = acc.z * inv + bb.z;
    o.w = acc.w * inv + bb.w;
    o.x = (o.x > 0.f) ? o.x : NEG_ACT * o.x;
    o.y = (o.y > 0.f) ? o.y : NEG_ACT * o.y;
    o.z = (o.z > 0.f) ? o.z : NEG_ACT * o.z;
    o.w = (o.w > 0.f) ? o.w : NEG_ACT * o.w;
    ((float4*)g_hb)[(size_t)n * 32 + l] = o;
}

// ---------------- GEMM2 + alpha2 fused: warp per node ----------------
__global__ void k_gemm2(const float* __restrict__ W2, const float* __restrict__ a2s,
                        const float* __restrict__ a2d, int N) {
    __shared__ float W2s[128 * 16];
    int t = threadIdx.x;
    for (int i = t; i < 2048; i += 256) W2s[i] = W2[i];
    __syncthreads();

    int warp = blockIdx.x * 8 + (t >> 5);
    if (warp >= N) return;
    int n = warp;
    int l = t & 31;
    int c = l & 15;
    int half = l >> 4;

    const float4* hb4 = (const float4*)(g_hb + (size_t)n * 128);
    float acc = 0.f;
#pragma unroll
    for (int k4 = 0; k4 < 16; k4++) {
        int kk = half * 16 + k4;
        float4 hv = hb4[kk];
        int k = kk * 4;
        acc = fmaf(hv.x, W2s[(k + 0) * 16 + c], acc);
        acc = fmaf(hv.y, W2s[(k + 1) * 16 + c], acc);
        acc = fmaf(hv.z, W2s[(k + 2) * 16 + c], acc);
        acc = fmaf(hv.w, W2s[(k + 3) * 16 + c], acc);
    }
    acc += __shfl_xor_sync(0xFFFFFFFFu, acc, 16);
    if (half == 0) g_h2[n * 16 + c] = acc;

    float vs = acc * __ldg(&a2s[c]);
    float vd = acc * __ldg(&a2d[c]);
#pragma unroll
    for (int off = 8; off; off >>= 1) {
        vs += __shfl_xor_sync(0xFFFFFFFFu, vs, off);
        vd += __shfl_xor_sync(0xFFFFFFFFu, vd, off);
    }
    if (l == 0) { g_as2[n] = vs; g_ad2[n] = vd; }
}

// ---------------- layer-2 gather + final softmax: warp per node ----------------
__global__ void k_gather2(const float* __restrict__ b2, float* __restrict__ out, int N) {
    int warp = blockIdx.x * 8 + (threadIdx.x >> 5);
    if (warp >= N) return;
    int n = warp;
    int l = threadIdx.x & 31;
    int c = l & 15;
    int half = l >> 4;
    int beg = g_rs[n];
    int end = g_rs[n + 1];
    int cnt = end - beg;
    float ad = g_ad2[n];

    // pass 1: max (all lanes redundantly)
    float mx = -1e30f;
    for (int i = beg; i < end; i++) {
        int s = g_esrc[i];
        float e = g_as2[s] + ad;
        e = (e > 0.f) ? e : NEG_ATT * e;
        mx = fmaxf(mx, e);
    }

    // pass 2: two edges per iteration (lanes 0-15 / 16-31)
    float acc = 0.f, ds = 0.f;
    for (int j = half; j < cnt; j += 2) {
        int s = g_esrc[beg + j];
        float e = g_as2[s] + ad;
        e = (e > 0.f) ? e : NEG_ATT * e;
        float ex = __expf(e - mx);
        float hv = g_h2[s * 16 + c];
        acc = fmaf(hv, ex, acc);
        ds += ex;
    }
    acc += __shfl_xor_sync(0xFFFFFFFFu, acc, 16);
    ds += __shfl_xor_sync(0xFFFFFFFFu, ds, 16);

    float o = acc / ds + __ldg(&b2[c]);
    // softmax over 16 classes (butterfly within 16-lane groups)
    float m = o;
#pragma unroll
    for (int off = 8; off; off >>= 1) m = fmaxf(m, __shfl_xor_sync(0xFFFFFFFFu, m, off));
    float ex = __expf(o - m);
    float sm = ex;
#pragma unroll
    for (int off = 8; off; off >>= 1) sm += __shfl_xor_sync(0xFFFFFFFFu, sm, off);
    if (l < 16) out[(size_t)n * 16 + c] = ex / sm;
}

// ---------------- launch ----------------
extern "C" void kernel_launch(void* const* d_in, const int* in_sizes, int n_in,
                              void* d_out, int out_size) {
    const float* x   = (const float*)d_in[0];
    const int*   ei  = (const int*)d_in[1];
    const float* W1  = (const float*)d_in[2];
    const float* a1s = (const float*)d_in[3];
    const float* a1d = (const float*)d_in[4];
    const float* b1  = (const float*)d_in[5];
    const float* W2  = (const float*)d_in[6];
    const float* a2s = (const float*)d_in[7];
    const float* a2d = (const float*)d_in[8];
    const float* b2  = (const float*)d_in[9];
    float* out = (float*)d_out;

    int N = in_sizes[0] / 128;
    int E = in_sizes[1] / 2;
    const int* src = ei;
    const int* dst = ei + E;

    int nbScan = (N + 511) / 512;

    // CSR build (by dst, self loop first)
    k_init_deg<<<(N + 255) / 256, 256>>>(N);
    k_hist<<<(E + 255) / 256, 256>>>(dst, E);
    k_scan1<<<nbScan, 512>>>(N);
    k_scan2<<<1, 1>>>(nbScan, N);
    k_scan3<<<nbScan, 512>>>(N);
    k_scatter<<<(E + 255) / 256, 256>>>(src, dst, E);

    // layer 1
    k_gemm1<<<(N + 31) / 32, 128>>>(x, W1, N);
    k_alpha1<<<(N * 8 + 255) / 256, 256>>>(a1s, a1d, N);
    k_gather1<<<(N + 7) / 8, 256>>>(b1, N);

    // layer 2
    k_gemm2<<<(N + 7) / 8, 256>>>(W2, a2s, a2d, N);
    k_gather2<<<(N + 7) / 8, 256>>>(b2, out, N);
}

// round 2
// speedup vs baseline: 1.0823x; 1.0823x over previous
#include <cuda_runtime.h>
#include <math.h>

#define MAXN 100000
#define MAXE 1600000
#define MAXET (MAXN + MAXE)

#define NEG_ATT 0.2f
#define NEG_ACT 0.01f

// ---------------- scratch ----------------
__device__ float g_h1[MAXN * 128];
__device__ float g_hb[MAXN * 128];
__device__ float g_as1[MAXN * 8];
__device__ float g_ad1[MAXN * 8];
__device__ float g_h2[MAXN * 16];
__device__ float g_as2[MAXN];
__device__ float g_ad2[MAXN];
__device__ int   g_deg[MAXN];       // degree WITHOUT self loop
__device__ int   g_rs[MAXN + 1];
__device__ int   g_cur[MAXN];
__device__ int   g_esrc[MAXET];
__device__ int   g_bsum[256];

// ---------------- f32x2 helpers ----------------
__device__ __forceinline__ unsigned long long ffma2(unsigned long long a,
                                                    unsigned long long b,
                                                    unsigned long long c) {
    unsigned long long d;
    asm("fma.rn.f32x2 %0, %1, %2, %3;" : "=l"(d) : "l"(a), "l"(b), "l"(c));
    return d;
}
__device__ __forceinline__ unsigned long long pack2(float a, float b) {
    unsigned long long r;
    asm("mov.b64 %0, {%1, %2};" : "=l"(r) : "f"(a), "f"(b));
    return r;
}
__device__ __forceinline__ float2 unpack2(unsigned long long v) {
    float2 r;
    asm("mov.b64 {%0, %1}, %2;" : "=f"(r.x), "=f"(r.y) : "l"(v));
    return r;
}

// ---------------- zero degrees ----------------
__global__ void k_zero(int N) {
    int i = blockIdx.x * blockDim.x + threadIdx.x;
    if (i < N) g_deg[i] = 0;
}

// ---------------- fat kernel: GEMM1 (FFMA2) + fused alpha1  ||  hist ----------------
// gemm blocks: 128 threads, thread t = output column, 32 nodes/block.
#define HIST_B 512
__global__ void k_fat(const float* __restrict__ x, const float* __restrict__ W,
                      const float* __restrict__ a1s, const float* __restrict__ a1d,
                      const int* __restrict__ dst, int N, int E, int GB) {
    if (blockIdx.x >= GB) {
        // histogram of dst degrees
        int b = blockIdx.x - GB;
        for (int e = b * 128 + threadIdx.x; e < E; e += 128 * HIST_B)
            atomicAdd(&g_deg[dst[e]], 1);
        return;
    }
    __shared__ float xs[32 * 128];
    int t = threadIdx.x;
    int n0 = blockIdx.x * 32;
    const float4* x4 = (const float4*)x;
    float4* xs4 = (float4*)xs;
    for (int i = t; i < 32 * 32; i += 128) {
        int row = i >> 5, c4 = i & 31;
        float4 v = make_float4(0.f, 0.f, 0.f, 0.f);
        if (n0 + row < N) v = x4[(size_t)(n0 + row) * 32 + c4];
        xs4[i] = v;
    }
    __syncthreads();

    unsigned long long acc2[32];  // (even-k partial, odd-k partial) per node
#pragma unroll
    for (int i = 0; i < 32; i++) acc2[i] = 0ULL;

    const ulonglong2* xsp = (const ulonglong2*)xs;
    for (int kq = 0; kq < 32; kq++) {  // k = 4*kq
        int k = kq * 4;
        float w0 = __ldg(&W[(k + 0) * 128 + t]);
        float w1 = __ldg(&W[(k + 1) * 128 + t]);
        float w2 = __ldg(&W[(k + 2) * 128 + t]);
        float w3 = __ldg(&W[(k + 3) * 128 + t]);
        unsigned long long wp0 = pack2(w0, w1);
        unsigned long long wp1 = pack2(w2, w3);
#pragma unroll
        for (int nl = 0; nl < 32; nl++) {
            ulonglong2 xv = xsp[nl * 32 + kq];
            acc2[nl] = ffma2(xv.x, wp0, acc2[nl]);
            acc2[nl] = ffma2(xv.y, wp1, acc2[nl]);
        }
    }

    // epilogue: h value, store, fused alpha reductions
    float asv = __ldg(&a1s[t]);   // a1s is [8][16] flat = index t
    float adv = __ldg(&a1d[t]);
    int hh = t >> 4;              // head
    int cc = t & 15;
#pragma unroll
    for (int nl = 0; nl < 32; nl++) {
        float2 p = unpack2(acc2[nl]);
        float h = p.x + p.y;
        float vs = h * asv;
        float vd = h * adv;
#pragma unroll
        for (int off = 8; off; off >>= 1) {
            vs += __shfl_xor_sync(0xFFFFFFFFu, vs, off);
            vd += __shfl_xor_sync(0xFFFFFFFFu, vd, off);
        }
        int n = n0 + nl;
        if (n < N) {
            g_h1[(size_t)n * 128 + t] = h;
            if (cc == 0) {
                g_as1[n * 8 + hh] = vs;
                g_ad1[n * 8 + hh] = vd;
            }
        }
    }
}

// ---------------- scans (degrees read as deg+1 for self loop) ----------------
__global__ void k_scan1(int N) {
    __shared__ int s[512];
    int t = threadIdx.x;
    int i = blockIdx.x * 512 + t;
    s[t] = (i < N) ? g_deg[i] + 1 : 0;
    __syncthreads();
    for (int off = 256; off; off >>= 1) {
        if (t < off) s[t] += s[t + off];
        __syncthreads();
    }
    if (t == 0) g_bsum[blockIdx.x] = s[0];
}

__global__ void k_scan2(int nb, int N) {
    __shared__ int sh[8];
    int t = threadIdx.x;
    int v = (t < nb) ? g_bsum[t] : 0;
    int lane = t & 31, w = t >> 5;
    int x = v;
#pragma unroll
    for (int off = 1; off < 32; off <<= 1) {
        int y = __shfl_up_sync(0xFFFFFFFFu, x, off);
        if (lane >= off) x += y;
    }
    if (lane == 31) sh[w] = x;
    __syncthreads();
    if (w == 0) {
        int y = (lane < 8) ? sh[lane] : 0;
#pragma unroll
        for (int off = 1; off < 8; off <<= 1) {
            int z = __shfl_up_sync(0xFFFFFFFFu, y, off);
            if (lane >= off) y += z;
        }
        if (lane < 8) sh[lane] = y;
    }
    __syncthreads();
    int incl = x + (w > 0 ? sh[w - 1] : 0);
    if (t < nb) g_bsum[t] = incl - v;      // exclusive
    if (t == nb - 1) g_rs[N] = incl;
}

__global__ void k_scan3(int N) {
    __shared__ int s[512];
    int t = threadIdx.x;
    int i = blockIdx.x * 512 + t;
    int v = (i < N) ? g_deg[i] + 1 : 0;
    s[t] = v;
    __syncthreads();
    for (int off = 1; off < 512; off <<= 1) {
        int x = (t >= off) ? s[t - off] : 0;
        __syncthreads();
        s[t] += x;
        __syncthreads();
    }
    int excl = s[t] - v;
    if (i < N) {
        int r = g_bsum[blockIdx.x] + excl;
        g_rs[i] = r;
        g_cur[i] = r + 1;   // slot 0 = self loop
        g_esrc[r] = i;
    }
}

__global__ void k_scatter(const int* __restrict__ src, const int* __restrict__ dst, int E) {
    int e = blockIdx.x * blockDim.x + threadIdx.x;
    if (e < E) {
        int p = atomicAdd(&g_cur[dst[e]], 1);
        g_esrc[p] = src[e];
    }
}

// ---------------- layer-1 gather: single-pass softmax (no max shift) ----------------
__global__ void k_gather1(const float* __restrict__ b1, int N) {
    int warp = blockIdx.x * 8 + (threadIdx.x >> 5);
    if (warp >= N) return;
    int n = warp;
    int l = threadIdx.x & 31;
    int h = l >> 2;
    int beg = g_rs[n];
    int end = g_rs[n + 1];
    float adh = g_ad1[n * 8 + h];

    const float4* h14 = (const float4*)g_h1;
    float4 acc = make_float4(0.f, 0.f, 0.f, 0.f);
    float ds = 0.f;
    int s_next = g_esrc[beg];
    for (int i = beg; i < end; i++) {
        int s = s_next;
        if (i + 1 < end) s_next = g_esrc[i + 1];
        float e = g_as1[s * 8 + h] + adh;
        e = (e > 0.f) ? e : NEG_ATT * e;
        float ex = __expf(e);
        float4 hv = h14[(size_t)s * 32 + l];
        acc.x = fmaf(hv.x, ex, acc.x);
        acc.y = fmaf(hv.y, ex, acc.y);
        acc.z = fmaf(hv.z, ex, acc.z);
        acc.w = fmaf(hv.w, ex, acc.w);
        ds += ex;
    }
    float inv = 1.f / ds;
    float4 bb = ((const float4*)b1)[l];
    float4 o;
    o.x = acc.x * inv + bb.x;
    o.y = acc.y * inv + bb.y;
    o.z = acc.z * inv + bb.z;
    o.w = acc.w * inv + bb.w;
    o.x = (o.x > 0.f) ? o.x : NEG_ACT * o.x;
    o.y = (o.y > 0.f) ? o.y : NEG_ACT * o.y;
    o.z = (o.z > 0.f) ? o.z : NEG_ACT * o.z;
    o.w = (o.w > 0.f) ? o.w : NEG_ACT * o.w;
    ((float4*)g_hb)[(size_t)n * 32 + l] = o;
}

// ---------------- GEMM2 + alpha2 fused ----------------
__global__ void k_gemm2(const float* __restrict__ W2, const float* __restrict__ a2s,
                        const float* __restrict__ a2d, int N) {
    __shared__ float W2s[128 * 16];
    int t = threadIdx.x;
    for (int i = t; i < 2048; i += 256) W2s[i] = W2[i];
    __syncthreads();

    int warp = blockIdx.x * 8 + (t >> 5);
    if (warp >= N) return;
    int n = warp;
    int l = t & 31;
    int c = l & 15;
    int half = l >> 4;

    const float4* hb4 = (const float4*)(g_hb + (size_t)n * 128);
    float acc = 0.f;
#pragma unroll
    for (int k4 = 0; k4 < 16; k4++) {
        int kk = half * 16 + k4;
        float4 hv = hb4[kk];
        int k = kk * 4;
        acc = fmaf(hv.x, W2s[(k + 0) * 16 + c], acc);
        acc = fmaf(hv.y, W2s[(k + 1) * 16 + c], acc);
        acc = fmaf(hv.z, W2s[(k + 2) * 16 + c], acc);
        acc = fmaf(hv.w, W2s[(k + 3) * 16 + c], acc);
    }
    acc += __shfl_xor_sync(0xFFFFFFFFu, acc, 16);
    if (half == 0) g_h2[n * 16 + c] = acc;

    float vs = acc * __ldg(&a2s[c]);
    float vd = acc * __ldg(&a2d[c]);
#pragma unroll
    for (int off = 8; off; off >>= 1) {
        vs += __shfl_xor_sync(0xFFFFFFFFu, vs, off);
        vd += __shfl_xor_sync(0xFFFFFFFFu, vd, off);
    }
    if (l == 0) { g_as2[n] = vs; g_ad2[n] = vd; }
}

// ---------------- layer-2 gather + final softmax: single pass ----------------
__global__ void k_gather2(const float* __restrict__ b2, float* __restrict__ out, int N) {
    int warp = blockIdx.x * 8 + (threadIdx.x >> 5);
    if (warp >= N) return;
    int n = warp;
    int l = threadIdx.x & 31;
    int c = l & 15;
    int half = l >> 4;
    int beg = g_rs[n];
    int cnt = g_rs[n + 1] - beg;
    float ad = g_ad2[n];

    float acc = 0.f, ds = 0.f;
    for (int j = half; j < cnt; j += 2) {
        int s = g_esrc[beg + j];
        float e = g_as2[s] + ad;
        e = (e > 0.f) ? e : NEG_ATT * e;
        float ex = __expf(e);
        float hv = g_h2[s * 16 + c];
        acc = fmaf(hv, ex, acc);
        ds += ex;
    }
    acc += __shfl_xor_sync(0xFFFFFFFFu, acc, 16);
    ds += __shfl_xor_sync(0xFFFFFFFFu, ds, 16);

    float o = acc / ds + __ldg(&b2[c]);
    float m = o;
#pragma unroll
    for (int off = 8; off; off >>= 1) m = fmaxf(m, __shfl_xor_sync(0xFFFFFFFFu, m, off));
    float ex = __expf(o - m);
    float sm = ex;
#pragma unroll
    for (int off = 8; off; off >>= 1) sm += __shfl_xor_sync(0xFFFFFFFFu, sm, off);
    if (l < 16) out[(size_t)n * 16 + c] = ex / sm;
}

// ---------------- launch ----------------
extern "C" void kernel_launch(void* const* d_in, const int* in_sizes, int n_in,
                              void* d_out, int out_size) {
    const float* x   = (const float*)d_in[0];
    const int*   ei  = (const int*)d_in[1];
    const float* W1  = (const float*)d_in[2];
    const float* a1s = (const float*)d_in[3];
    const float* a1d = (const float*)d_in[4];
    const float* b1  = (const float*)d_in[5];
    const float* W2  = (const float*)d_in[6];
    const float* a2s = (const float*)d_in[7];
    const float* a2d = (const float*)d_in[8];
    const float* b2  = (const float*)d_in[9];
    float* out = (float*)d_out;

    int N = in_sizes[0] / 128;
    int E = in_sizes[1] / 2;
    const int* src = ei;
    const int* dst = ei + E;

    int nbScan = (N + 511) / 512;
    int GB = (N + 31) / 32;

    k_zero<<<(N + 511) / 512, 512>>>(N);
    // GEMM1 (+fused alpha1) overlapped with degree histogram
    k_fat<<<GB + HIST_B, 128>>>(x, W1, a1s, a1d, dst, N, E, GB);
    k_scan1<<<nbScan, 512>>>(N);
    k_scan2<<<1, 256>>>(nbScan, N);
    k_scan3<<<nbScan, 512>>>(N);
    k_scatter<<<(E + 255) / 256, 256>>>(src, dst, E);

    k_gather1<<<(N + 7) / 8, 256>>>(b1, N);
    k_gemm2<<<(N + 7) / 8, 256>>>(W2, a2s, a2d, N);
    k_gather2<<<(N + 7) / 8, 256>>>(b2, out, N);
}